// round 4
// baseline (speedup 1.0000x reference)
#include <cuda_runtime.h>
#include <stdint.h>

// Problem constants (fixed shapes for this problem)
constexpr int S_DIM = 16384;   // s
constexpr int T_DIM = 8192;    // t
constexpr int B_DIM = 16;      // batch
constexpr int NH    = 16;      // top-k
constexpr int KEEP  = 24;      // candidates kept at each rebuild (margin over NH for sqrt ties)
constexpr int CAP   = 128;     // per-warp candidate buffer capacity
constexpr int TRIG  = 96;      // rebuild trigger (TRIG + 32 <= CAP)
constexpr unsigned FULLM = 0xFFFFFFFFu;

// Output layout (float32 concat of the tuple):
constexpr size_t OFF_XNEAR = 0;                               // [16][8192][16][1]
constexpr size_t OFF_IDIST = (size_t)B_DIM * T_DIM * NH;      // 2097152
constexpr size_t OFF_ILON  = OFF_IDIST + (size_t)T_DIM * NH;  // 2228224
constexpr size_t OFF_ILAT  = OFF_ILON  + (size_t)T_DIM * NH;  // 2359296

// Pack (nonnegative float value, index) into a u64 whose unsigned order is
// (value ascending, index ascending) — exactly jax.lax.top_k's stable order.
__device__ __forceinline__ unsigned long long pack_key(float v, unsigned idx) {
    return ((unsigned long long)__float_as_uint(v) << 32) | idx;
}

__device__ __forceinline__ unsigned long long warp_min64(unsigned long long v) {
    #pragma unroll
    for (int o = 16; o > 0; o >>= 1) {
        unsigned long long w = __shfl_xor_sync(FULLM, v, o);
        if (w < v) v = w;
    }
    return v;
}

// Warp-collective: select `rounds` smallest keys from buf[0..cnt), write them
// sorted ascending into buf[0..rounds). Returns the rounds-th smallest key.
// Keys are unique (distinct low-32 indices), so ownership resolution is exact.
__device__ __forceinline__ unsigned long long select_sorted(
    unsigned long long* buf, int cnt, int rounds, int lane)
{
    unsigned long long k[CAP / 32];
    unsigned long long lmin = ~0ull;
    #pragma unroll
    for (int q = 0; q < CAP / 32; q++) {
        int p = lane + 32 * q;
        k[q] = (p < cnt) ? buf[p] : ~0ull;
        if (k[q] < lmin) lmin = k[q];
    }
    unsigned long long g = ~0ull;
    for (int r = 0; r < rounds; r++) {
        g = warp_min64(lmin);
        if (lmin == g) {                 // unique owner (keys unique)
            unsigned long long nl = ~0ull;
            #pragma unroll
            for (int q = 0; q < CAP / 32; q++) {
                if (k[q] == g) k[q] = ~0ull;
                if (k[q] < nl) nl = k[q];
            }
            lmin = nl;
        }
        if (lane == 0) buf[r] = g;
    }
    __syncwarp();
    return g;
}

// Warp-collective append of passing elements into the candidate buffer.
// cnt/thr are warp-uniform registers. Rebuild keeps KEEP best and tightens thr.
// Max growth between rebuild checks: 32; so cnt <= TRIG+32 = CAP always.
__device__ __forceinline__ void try_append(bool p, float v, unsigned idx,
    unsigned long long* buf, int& cnt, float& thr, int lane)
{
    unsigned m = __ballot_sync(FULLM, p);
    if (m == 0) return;
    if (p) buf[cnt + __popc(m & ((1u << lane) - 1u))] = pack_key(v, idx);
    cnt += __popc(m);
    if (cnt > TRIG) {
        __syncwarp();
        unsigned long long g = select_sorted(buf, cnt, KEEP, lane);
        cnt = KEEP;
        thr = __uint_as_float((unsigned)(g >> 32));   // KEEP-th best value; compare is inclusive
    }
}

__global__ __launch_bounds__(96)
void nn_topk_kernel(const float* __restrict__ x,
                    const float* __restrict__ dlon,
                    const float* __restrict__ dlat,
                    float* __restrict__ out)
{
    __shared__ unsigned long long sbuf[3][CAP];

    const int row  = blockIdx.x;
    const int warp = threadIdx.x >> 5;
    const int lane = threadIdx.x & 31;
    unsigned long long* buf = sbuf[warp];

    float thr = __int_as_float(0x7f800000);  // +inf: accept-all until first rebuild
    int cnt = 0;

    if (warp == 0) {
        // ---- criterion: euclidean distance (scan on squared distance) ----
        // 512 elements per outer iteration: 8 independent LDG.128 front-batched,
        // FMNMX min-tree, ONE vote + ONE branch region on the common path.
        const float4* Pa = reinterpret_cast<const float4*>(dlon + (size_t)row * S_DIM);
        const float4* Pb = reinterpret_cast<const float4*>(dlat + (size_t)row * S_DIM);
        #pragma unroll 1
        for (int it = 0; it < S_DIM / 512; ++it) {
            float4 a[4], b[4];
            #pragma unroll
            for (int q = 0; q < 4; q++) a[q] = Pa[it * 128 + q * 32 + lane];
            #pragma unroll
            for (int q = 0; q < 4; q++) b[q] = Pb[it * 128 + q * 32 + lane];
            float s[16];
            #pragma unroll
            for (int q = 0; q < 4; q++) {
                s[q*4+0] = fmaf(a[q].x, a[q].x, b[q].x * b[q].x);
                s[q*4+1] = fmaf(a[q].y, a[q].y, b[q].y * b[q].y);
                s[q*4+2] = fmaf(a[q].z, a[q].z, b[q].z * b[q].z);
                s[q*4+3] = fmaf(a[q].w, a[q].w, b[q].w * b[q].w);
            }
            // min-tree (FMNMX, fixed-lat alu; values are nonneg, no NaN)
            float m01 = fminf(fminf(s[0], s[1]), fminf(s[2], s[3]));
            float m23 = fminf(fminf(s[4], s[5]), fminf(s[6], s[7]));
            float m45 = fminf(fminf(s[8], s[9]), fminf(s[10], s[11]));
            float m67 = fminf(fminf(s[12], s[13]), fminf(s[14], s[15]));
            float mn  = fminf(fminf(m01, m23), fminf(m45, m67));
            if (__any_sync(FULLM, mn <= thr)) {            // rare after warmup
                #pragma unroll
                for (int q = 0; q < 4; q++) {
                    unsigned base = (unsigned)(it * 512 + q * 128) + (unsigned)lane * 4u;
                    try_append(s[q*4+0] <= thr, s[q*4+0], base + 0u, buf, cnt, thr, lane);
                    try_append(s[q*4+1] <= thr, s[q*4+1], base + 1u, buf, cnt, thr, lane);
                    try_append(s[q*4+2] <= thr, s[q*4+2], base + 2u, buf, cnt, thr, lane);
                    try_append(s[q*4+3] <= thr, s[q*4+3], base + 3u, buf, cnt, thr, lane);
                }
            }
        }
        // Re-key survivors with exact IEEE sqrt so final order matches reference.
        __syncwarp();
        for (int p = lane; p < cnt; p += 32) {
            unsigned long long e = buf[p];
            float d = __fsqrt_rn(__uint_as_float((unsigned)(e >> 32)));
            buf[p] = pack_key(d, (unsigned)e);
        }
        __syncwarp();
        select_sorted(buf, cnt, NH, lane);   // buf[0..15] = final sorted keys

        // indices_dist (as float)
        if (lane < NH) {
            unsigned idx = (unsigned)buf[lane];
            out[OFF_IDIST + (size_t)row * NH + lane] = (float)idx;
        }
        __syncwarp();
        // x_nearest gather: out[b][row][j] = x[b][idx_j]   (e == 1)
        #pragma unroll
        for (int p = lane; p < B_DIM * NH; p += 32) {
            int b = p >> 4;
            int j = p & 15;
            unsigned idx = (unsigned)buf[j];
            out[OFF_XNEAR + (size_t)b * (T_DIM * NH) + (size_t)row * NH + j] =
                x[(size_t)b * S_DIM + idx];
        }
    } else {
        // ---- criterion: |d_lon| (warp 1) or |d_lat| (warp 2) ----
        const float* src = (warp == 1) ? dlon : dlat;
        const float4* Pa = reinterpret_cast<const float4*>(src + (size_t)row * S_DIM);
        #pragma unroll 1
        for (int it = 0; it < S_DIM / 512; ++it) {
            float4 a[4];
            #pragma unroll
            for (int q = 0; q < 4; q++) a[q] = Pa[it * 128 + q * 32 + lane];
            // min-of-abs tree: |x| folds into FMNMX operand modifiers (free)
            float m[4];
            #pragma unroll
            for (int q = 0; q < 4; q++)
                m[q] = fminf(fminf(fabsf(a[q].x), fabsf(a[q].y)),
                             fminf(fabsf(a[q].z), fabsf(a[q].w)));
            float mn = fminf(fminf(m[0], m[1]), fminf(m[2], m[3]));
            if (__any_sync(FULLM, mn <= thr)) {            // rare after warmup
                #pragma unroll
                for (int q = 0; q < 4; q++) {
                    unsigned base = (unsigned)(it * 512 + q * 128) + (unsigned)lane * 4u;
                    float a0 = fabsf(a[q].x), a1 = fabsf(a[q].y);
                    float a2 = fabsf(a[q].z), a3 = fabsf(a[q].w);
                    try_append(a0 <= thr, a0, base + 0u, buf, cnt, thr, lane);
                    try_append(a1 <= thr, a1, base + 1u, buf, cnt, thr, lane);
                    try_append(a2 <= thr, a2, base + 2u, buf, cnt, thr, lane);
                    try_append(a3 <= thr, a3, base + 3u, buf, cnt, thr, lane);
                }
            }
        }
        __syncwarp();
        select_sorted(buf, cnt, NH, lane);
        const size_t obase = (warp == 1) ? OFF_ILON : OFF_ILAT;
        if (lane < NH) {
            unsigned idx = (unsigned)buf[lane];
            out[obase + (size_t)row * NH + lane] = (float)idx;
        }
    }
}

extern "C" void kernel_launch(void* const* d_in, const int* in_sizes, int n_in,
                              void* d_out, int out_size) {
    (void)in_sizes; (void)n_in; (void)out_size;
    const float* x    = (const float*)d_in[0];
    const float* dlon = (const float*)d_in[1];
    const float* dlat = (const float*)d_in[2];
    nn_topk_kernel<<<T_DIM, 96>>>(x, dlon, dlat, (float*)d_out);
}

// round 8
// speedup vs baseline: 1.2701x; 1.2701x over previous
#include <cuda_runtime.h>
#include <stdint.h>

constexpr int S_DIM = 16384;
constexpr int T_DIM = 8192;
constexpr int B_DIM = 16;
constexpr int NH    = 16;
constexpr int KEEP  = 24;
constexpr int CAP   = 128;
constexpr int TRIG  = 96;
constexpr unsigned FULLM = 0xFFFFFFFFu;

constexpr size_t OFF_XNEAR = 0;
constexpr size_t OFF_IDIST = (size_t)B_DIM * T_DIM * NH;      // 2097152
constexpr size_t OFF_ILON  = OFF_IDIST + (size_t)T_DIM * NH;  // 2228224
constexpr size_t OFF_ILAT  = OFF_ILON  + (size_t)T_DIM * NH;  // 2359296

// Pack (nonneg float, index): unsigned order == (value asc, index asc),
// exactly jax.lax.top_k's stable order.
__device__ __forceinline__ unsigned long long pack_key(float v, unsigned idx) {
    return ((unsigned long long)__float_as_uint(v) << 32) | idx;
}

__device__ __forceinline__ unsigned long long warp_min64(unsigned long long v) {
    #pragma unroll
    for (int o = 16; o > 0; o >>= 1) {
        unsigned long long w = __shfl_xor_sync(FULLM, v, o);
        if (w < v) v = w;
    }
    return v;
}

// Warp-collective: write `rounds` smallest keys of buf[0..cnt) sorted into
// buf[0..rounds); returns the rounds-th smallest. Keys unique (distinct idx).
__device__ __forceinline__ unsigned long long select_sorted(
    unsigned long long* buf, int cnt, int rounds, int lane)
{
    unsigned long long k[CAP / 32];
    unsigned long long lmin = ~0ull;
    #pragma unroll
    for (int q = 0; q < CAP / 32; q++) {
        int p = lane + 32 * q;
        k[q] = (p < cnt) ? buf[p] : ~0ull;
        if (k[q] < lmin) lmin = k[q];
    }
    unsigned long long g = ~0ull;
    for (int r = 0; r < rounds; r++) {
        g = warp_min64(lmin);
        if (lmin == g) {
            unsigned long long nl = ~0ull;
            #pragma unroll
            for (int q = 0; q < CAP / 32; q++) {
                if (k[q] == g) k[q] = ~0ull;
                if (k[q] < nl) nl = k[q];
            }
            lmin = nl;
        }
        if (lane == 0) buf[r] = g;
    }
    __syncwarp();
    return g;
}

// Append passing lanes; rebuild keeps KEEP best and tightens thr (inclusive).
// cnt <= 96 before any append; +32 max => writes bounded by CAP.
__device__ __forceinline__ void try_append(bool p, float v, unsigned idx,
    unsigned long long* buf, int& cnt, float& thr, int lane)
{
    unsigned m = __ballot_sync(FULLM, p);
    if (m == 0) return;
    if (p) buf[cnt + __popc(m & ((1u << lane) - 1u))] = pack_key(v, idx);
    cnt += __popc(m);
    if (cnt > TRIG) {
        __syncwarp();
        unsigned long long g = select_sorted(buf, cnt, KEEP, lane);
        cnt = KEEP;
        thr = __uint_as_float((unsigned)(g >> 32));
    }
}

// Filter one 128-element group given its 4 per-lane values.
__device__ __forceinline__ void filt4(float s0, float s1, float s2, float s3,
    unsigned base, unsigned long long* buf, int& cnt, float& thr, int lane)
{
    try_append(s0 <= thr, s0, base + 0u, buf, cnt, thr, lane);
    try_append(s1 <= thr, s1, base + 1u, buf, cnt, thr, lane);
    try_append(s2 <= thr, s2, base + 2u, buf, cnt, thr, lane);
    try_append(s3 <= thr, s3, base + 3u, buf, cnt, thr, lane);
}

__global__ __launch_bounds__(96)
void nn_topk_kernel(const float* __restrict__ x,
                    const float* __restrict__ dlon,
                    const float* __restrict__ dlat,
                    float* __restrict__ out)
{
    __shared__ unsigned long long sbuf[3][CAP];

    const int row  = blockIdx.x;
    const int warp = threadIdx.x >> 5;
    const int lane = threadIdx.x & 31;
    unsigned long long* buf = sbuf[warp];

    float thr = __int_as_float(0x7f800000);  // +inf until first rebuild
    int cnt = 0;

    if (warp == 0) {
        // ---- euclidean distance: scan squared values, 256 elems/iter,
        //      depth-1 software pipeline (prefetch next iter's 4 LDG.128) ----
        const float4* Pa = reinterpret_cast<const float4*>(dlon + (size_t)row * S_DIM);
        const float4* Pb = reinterpret_cast<const float4*>(dlat + (size_t)row * S_DIM);
        constexpr int NIT = S_DIM / 256;   // 64
        float4 a0 = Pa[lane], a1 = Pa[32 + lane];
        float4 b0 = Pb[lane], b1 = Pb[32 + lane];
        #pragma unroll 1
        for (int it = 0; it < NIT; ++it) {
            float4 na0, na1, nb0, nb1;
            if (it + 1 < NIT) {             // prefetch issues BEFORE compute
                na0 = Pa[(it + 1) * 64 + lane];
                na1 = Pa[(it + 1) * 64 + 32 + lane];
                nb0 = Pb[(it + 1) * 64 + lane];
                nb1 = Pb[(it + 1) * 64 + 32 + lane];
            }
            float s0 = fmaf(a0.x, a0.x, b0.x * b0.x);
            float s1 = fmaf(a0.y, a0.y, b0.y * b0.y);
            float s2 = fmaf(a0.z, a0.z, b0.z * b0.z);
            float s3 = fmaf(a0.w, a0.w, b0.w * b0.w);
            float s4 = fmaf(a1.x, a1.x, b1.x * b1.x);
            float s5 = fmaf(a1.y, a1.y, b1.y * b1.y);
            float s6 = fmaf(a1.z, a1.z, b1.z * b1.z);
            float s7 = fmaf(a1.w, a1.w, b1.w * b1.w);
            float mn = fminf(fminf(fminf(s0, s1), fminf(s2, s3)),
                             fminf(fminf(s4, s5), fminf(s6, s7)));
            if (__any_sync(FULLM, mn <= thr)) {     // rare once thr tightens
                unsigned base = (unsigned)(it * 256) + (unsigned)lane * 4u;
                filt4(s0, s1, s2, s3, base,        buf, cnt, thr, lane);
                filt4(s4, s5, s6, s7, base + 128u, buf, cnt, thr, lane);
            }
            a0 = na0; a1 = na1; b0 = nb0; b1 = nb1;
        }
        // Re-key survivors with exact IEEE sqrt (order matches reference).
        __syncwarp();
        for (int p = lane; p < cnt; p += 32) {
            unsigned long long e = buf[p];
            float d = __fsqrt_rn(__uint_as_float((unsigned)(e >> 32)));
            buf[p] = pack_key(d, (unsigned)e);
        }
        __syncwarp();
        select_sorted(buf, cnt, NH, lane);

        if (lane < NH) {
            unsigned idx = (unsigned)buf[lane];
            out[OFF_IDIST + (size_t)row * NH + lane] = (float)idx;
        }
        __syncwarp();
        #pragma unroll
        for (int p = lane; p < B_DIM * NH; p += 32) {
            int b = p >> 4;
            int j = p & 15;
            unsigned idx = (unsigned)buf[j];
            out[OFF_XNEAR + (size_t)b * (T_DIM * NH) + (size_t)row * NH + j] =
                x[(size_t)b * S_DIM + idx];
        }
    } else {
        // ---- |d_lon| (warp 1) / |d_lat| (warp 2): 512 elems/iter,
        //      depth-1 pipeline (4 LDG.128 prefetched) ----
        const float* src = (warp == 1) ? dlon : dlat;
        const float4* Pa = reinterpret_cast<const float4*>(src + (size_t)row * S_DIM);
        constexpr int NIT = S_DIM / 512;   // 32
        float4 a0 = Pa[lane], a1 = Pa[32 + lane];
        float4 a2 = Pa[64 + lane], a3 = Pa[96 + lane];
        #pragma unroll 1
        for (int it = 0; it < NIT; ++it) {
            float4 n0, n1, n2, n3;
            if (it + 1 < NIT) {
                n0 = Pa[(it + 1) * 128 + lane];
                n1 = Pa[(it + 1) * 128 + 32 + lane];
                n2 = Pa[(it + 1) * 128 + 64 + lane];
                n3 = Pa[(it + 1) * 128 + 96 + lane];
            }
            float m0 = fminf(fminf(fabsf(a0.x), fabsf(a0.y)), fminf(fabsf(a0.z), fabsf(a0.w)));
            float m1 = fminf(fminf(fabsf(a1.x), fabsf(a1.y)), fminf(fabsf(a1.z), fabsf(a1.w)));
            float m2 = fminf(fminf(fabsf(a2.x), fabsf(a2.y)), fminf(fabsf(a2.z), fabsf(a2.w)));
            float m3 = fminf(fminf(fabsf(a3.x), fabsf(a3.y)), fminf(fabsf(a3.z), fabsf(a3.w)));
            float mn = fminf(fminf(m0, m1), fminf(m2, m3));
            if (__any_sync(FULLM, mn <= thr)) {
                unsigned base = (unsigned)(it * 512) + (unsigned)lane * 4u;
                filt4(fabsf(a0.x), fabsf(a0.y), fabsf(a0.z), fabsf(a0.w), base,        buf, cnt, thr, lane);
                filt4(fabsf(a1.x), fabsf(a1.y), fabsf(a1.z), fabsf(a1.w), base + 128u, buf, cnt, thr, lane);
                filt4(fabsf(a2.x), fabsf(a2.y), fabsf(a2.z), fabsf(a2.w), base + 256u, buf, cnt, thr, lane);
                filt4(fabsf(a3.x), fabsf(a3.y), fabsf(a3.z), fabsf(a3.w), base + 384u, buf, cnt, thr, lane);
            }
            a0 = n0; a1 = n1; a2 = n2; a3 = n3;
        }
        __syncwarp();
        select_sorted(buf, cnt, NH, lane);
        const size_t obase = (warp == 1) ? OFF_ILON : OFF_ILAT;
        if (lane < NH) {
            unsigned idx = (unsigned)buf[lane];
            out[obase + (size_t)row * NH + lane] = (float)idx;
        }
    }
}

extern "C" void kernel_launch(void* const* d_in, const int* in_sizes, int n_in,
                              void* d_out, int out_size) {
    (void)in_sizes; (void)n_in; (void)out_size;
    const float* x    = (const float*)d_in[0];
    const float* dlon = (const float*)d_in[1];
    const float* dlat = (const float*)d_in[2];
    nn_topk_kernel<<<T_DIM, 96>>>(x, dlon, dlat, (float*)d_out);
}

// round 9
// speedup vs baseline: 4.1217x; 3.2452x over previous
#include <cuda_runtime.h>
#include <stdint.h>

constexpr int S_DIM = 16384;
constexpr int T_DIM = 8192;
constexpr int B_DIM = 16;
constexpr int NH    = 16;
constexpr int KEEP  = 24;
constexpr int CAP   = 128;
constexpr int TRIG  = 96;
constexpr unsigned FULLM = 0xFFFFFFFFu;

constexpr size_t OFF_XNEAR = 0;
constexpr size_t OFF_IDIST = (size_t)B_DIM * T_DIM * NH;      // 2097152
constexpr size_t OFF_ILON  = OFF_IDIST + (size_t)T_DIM * NH;  // 2228224
constexpr size_t OFF_ILAT  = OFF_ILON  + (size_t)T_DIM * NH;  // 2359296

// cp.async helpers: per-thread 16B global->shared copies with group tracking.
__device__ __forceinline__ unsigned saddr(const void* p) {
    return (unsigned)__cvta_generic_to_shared(p);
}
#define CP16(dst_s, src_g) \
    asm volatile("cp.async.cg.shared.global [%0], [%1], 16;" :: "r"(dst_s), "l"(src_g))
#define CPCOMMIT() asm volatile("cp.async.commit_group;" ::: "memory")
#define CPWAIT6()  asm volatile("cp.async.wait_group 6;"  ::: "memory")

// Pack (nonneg float, index): unsigned order == (value asc, index asc),
// exactly jax.lax.top_k's stable order.
__device__ __forceinline__ unsigned long long pack_key(float v, unsigned idx) {
    return ((unsigned long long)__float_as_uint(v) << 32) | idx;
}

__device__ __forceinline__ unsigned long long warp_min64(unsigned long long v) {
    #pragma unroll
    for (int o = 16; o > 0; o >>= 1) {
        unsigned long long w = __shfl_xor_sync(FULLM, v, o);
        if (w < v) v = w;
    }
    return v;
}

// Warp-collective: write `rounds` smallest keys of buf[0..cnt) sorted into
// buf[0..rounds); returns the rounds-th smallest. Keys unique (distinct idx).
__device__ __forceinline__ unsigned long long select_sorted(
    unsigned long long* buf, int cnt, int rounds, int lane)
{
    unsigned long long k[CAP / 32];
    unsigned long long lmin = ~0ull;
    #pragma unroll
    for (int q = 0; q < CAP / 32; q++) {
        int p = lane + 32 * q;
        k[q] = (p < cnt) ? buf[p] : ~0ull;
        if (k[q] < lmin) lmin = k[q];
    }
    unsigned long long g = ~0ull;
    for (int r = 0; r < rounds; r++) {
        g = warp_min64(lmin);
        if (lmin == g) {
            unsigned long long nl = ~0ull;
            #pragma unroll
            for (int q = 0; q < CAP / 32; q++) {
                if (k[q] == g) k[q] = ~0ull;
                if (k[q] < nl) nl = k[q];
            }
            lmin = nl;
        }
        if (lane == 0) buf[r] = g;
    }
    __syncwarp();
    return g;
}

// Append passing lanes; rebuild keeps KEEP best and tightens thr (inclusive).
// cnt <= TRIG before any append; +32 max => writes bounded by CAP.
__device__ __forceinline__ void try_append(bool p, float v, unsigned idx,
    unsigned long long* buf, int& cnt, float& thr, int lane)
{
    unsigned m = __ballot_sync(FULLM, p);
    if (m == 0) return;
    if (p) buf[cnt + __popc(m & ((1u << lane) - 1u))] = pack_key(v, idx);
    cnt += __popc(m);
    if (cnt > TRIG) {
        __syncwarp();
        unsigned long long g = select_sorted(buf, cnt, KEEP, lane);
        cnt = KEEP;
        thr = __uint_as_float((unsigned)(g >> 32));
    }
}

__global__ __launch_bounds__(96)
void nn_topk_kernel(const float* __restrict__ x,
                    const float* __restrict__ dlon,
                    const float* __restrict__ dlat,
                    float* __restrict__ out)
{
    // Per-warp smem rings: 8 slots x 32 lanes x float4. ringA: all 3 warps'
    // primary stream; ringB: warp0's second stream (dlat).
    __shared__ float4 ringA[3][8][32];
    __shared__ float4 ringB[8][32];
    __shared__ unsigned long long sbuf[3][CAP];

    const int row  = blockIdx.x;
    const int warp = threadIdx.x >> 5;
    const int lane = threadIdx.x & 31;
    unsigned long long* buf = sbuf[warp];

    float thr = __int_as_float(0x7f800000);  // +inf until first rebuild
    int cnt = 0;

    // Primary stream: warp0 & warp1 scan dlon; warp2 scans dlat.
    const float* srcA = (warp == 2) ? (dlat + (size_t)row * S_DIM)
                                    : (dlon + (size_t)row * S_DIM);
    const float* srcB = dlat + (size_t)row * S_DIM;   // warp0 only

    constexpr int NIT = S_DIM / 128;   // 128 chunks of 128 elements

    // Prologue: fill pipeline with chunks 0..6 (one commit group per chunk).
    #pragma unroll
    for (int p = 0; p < 7; ++p) {
        CP16(saddr(&ringA[warp][p][lane]), srcA + p * 128 + lane * 4);
        if (warp == 0)
            CP16(saddr(&ringB[p][lane]), srcB + p * 128 + lane * 4);
        CPCOMMIT();
    }

    if (warp == 0) {
        // ---- euclidean distance: scan squared values (monotone under sqrt) ----
        #pragma unroll 1
        for (int it = 0; it < NIT; ++it) {
            CPWAIT6();                                  // chunk `it` resident
            float4 a = ringA[0][it & 7][lane];
            float4 b = ringB[it & 7][lane];
            int nx = it + 7;                            // refill (slot != read slot)
            if (nx < NIT) {
                CP16(saddr(&ringA[0][nx & 7][lane]), srcA + nx * 128 + lane * 4);
                CP16(saddr(&ringB[nx & 7][lane]),    srcB + nx * 128 + lane * 4);
            }
            CPCOMMIT();                                 // uniform group count
            float s0 = fmaf(a.x, a.x, b.x * b.x);
            float s1 = fmaf(a.y, a.y, b.y * b.y);
            float s2 = fmaf(a.z, a.z, b.z * b.z);
            float s3 = fmaf(a.w, a.w, b.w * b.w);
            float mn = fminf(fminf(s0, s1), fminf(s2, s3));
            if (__any_sync(FULLM, mn <= thr)) {         // rare once thr tightens
                unsigned base = (unsigned)(it * 128) + (unsigned)lane * 4u;
                try_append(s0 <= thr, s0, base + 0u, buf, cnt, thr, lane);
                try_append(s1 <= thr, s1, base + 1u, buf, cnt, thr, lane);
                try_append(s2 <= thr, s2, base + 2u, buf, cnt, thr, lane);
                try_append(s3 <= thr, s3, base + 3u, buf, cnt, thr, lane);
            }
        }
        // Re-key survivors with exact IEEE sqrt (order matches reference).
        __syncwarp();
        for (int p = lane; p < cnt; p += 32) {
            unsigned long long e = buf[p];
            float d = __fsqrt_rn(__uint_as_float((unsigned)(e >> 32)));
            buf[p] = pack_key(d, (unsigned)e);
        }
        __syncwarp();
        select_sorted(buf, cnt, NH, lane);   // buf[0..15] = final sorted keys

        if (lane < NH) {
            unsigned idx = (unsigned)buf[lane];
            out[OFF_IDIST + (size_t)row * NH + lane] = (float)idx;
        }
        __syncwarp();
        // x_nearest gather: out[b][row][j] = x[b][idx_j]   (e == 1)
        #pragma unroll
        for (int p = lane; p < B_DIM * NH; p += 32) {
            int b = p >> 4;
            int j = p & 15;
            unsigned idx = (unsigned)buf[j];
            out[OFF_XNEAR + (size_t)b * (T_DIM * NH) + (size_t)row * NH + j] =
                x[(size_t)b * S_DIM + idx];
        }
    } else {
        // ---- |d_lon| (warp 1) / |d_lat| (warp 2) ----
        #pragma unroll 1
        for (int it = 0; it < NIT; ++it) {
            CPWAIT6();
            float4 a = ringA[warp][it & 7][lane];
            int nx = it + 7;
            if (nx < NIT)
                CP16(saddr(&ringA[warp][nx & 7][lane]), srcA + nx * 128 + lane * 4);
            CPCOMMIT();
            float a0 = fabsf(a.x), a1 = fabsf(a.y), a2 = fabsf(a.z), a3 = fabsf(a.w);
            float mn = fminf(fminf(a0, a1), fminf(a2, a3));
            if (__any_sync(FULLM, mn <= thr)) {
                unsigned base = (unsigned)(it * 128) + (unsigned)lane * 4u;
                try_append(a0 <= thr, a0, base + 0u, buf, cnt, thr, lane);
                try_append(a1 <= thr, a1, base + 1u, buf, cnt, thr, lane);
                try_append(a2 <= thr, a2, base + 2u, buf, cnt, thr, lane);
                try_append(a3 <= thr, a3, base + 3u, buf, cnt, thr, lane);
            }
        }
        __syncwarp();
        select_sorted(buf, cnt, NH, lane);
        const size_t obase = (warp == 1) ? OFF_ILON : OFF_ILAT;
        if (lane < NH) {
            unsigned idx = (unsigned)buf[lane];
            out[obase + (size_t)row * NH + lane] = (float)idx;
        }
    }
}

extern "C" void kernel_launch(void* const* d_in, const int* in_sizes, int n_in,
                              void* d_out, int out_size) {
    (void)in_sizes; (void)n_in; (void)out_size;
    const float* x    = (const float*)d_in[0];
    const float* dlon = (const float*)d_in[1];
    const float* dlat = (const float*)d_in[2];
    nn_topk_kernel<<<T_DIM, 96>>>(x, dlon, dlat, (float*)d_out);
}